// round 13
// baseline (speedup 1.0000x reference)
#include <cuda_runtime.h>

// CapsuleLayer dynamic routing. C=10,B=128,N=1152,IN=8,OUT=16, 3 iters.
//   1) tiled transpose W -> Wt4[c][j][n]; simple transpose x -> xT4[b][j][n]
//   2) fused priors + routing, one CTA per (c, batch-pair), 576 threads.
// All priors register-resident (4x16 regs/thread). ONE barrier per routing
// iteration: after the per-warp butterfly lands in (double-buffered) vred,
// EVERY warp redundantly computes the identical 18-way reduce + squash and
// writes bit-identical outv values (benign identical-value race; pure
// deterministic FP). Shift-free softmax (exact), fused logit-update sweeps;
// iteration 0 uses logits==0 -> uniform attention (S = N).

#define CCAP   10
#define BD     128
#define ND     1152
#define OUTD   16
#define HALF   576
#define THREADS 576
#define NWARPS  18
#define NBLOCKS (CCAP * BD / 2)   // 640

#define WT_ELEMS (CCAP * 32 * ND)   // 368,640 float4 (5.9 MB)
#define XT_ELEMS (BD * 2 * ND)      // 294,912 float4 (4.7 MB)

__device__ float4 g_Wt[WT_ELEMS];
__device__ float4 g_xT[XT_ELEMS];

// ---------------- Kernel 1: transposes ----------------
#define TP_WBLOCKS (CCAP * 36)          // 360
#define TP_XBLOCKS (XT_ELEMS / 1024)    // 288

__global__ void transpose_inputs_kernel(const float4* __restrict__ W4,
                                        const float4* __restrict__ X4)
{
    if (blockIdx.x < TP_WBLOCKS) {
        __shared__ float4 tile[32][33];
        const int c  = blockIdx.x / 36;
        const int n0 = (blockIdx.x % 36) * 32;
        #pragma unroll
        for (int k = 0; k < 4; k++) {
            int flat = threadIdx.x + k * 256;
            int jr = flat & 31, nr = flat >> 5;
            tile[jr][nr] = W4[((size_t)(c * ND + n0 + nr)) * 32 + jr];
        }
        __syncthreads();
        #pragma unroll
        for (int k = 0; k < 4; k++) {
            int flat = threadIdx.x + k * 256;
            int nr = flat & 31, jr = flat >> 5;
            g_Wt[(size_t)(c * 32 + jr) * ND + n0 + nr] = tile[jr][nr];
        }
    } else {
        int base = (blockIdx.x - TP_WBLOCKS) * 1024 + threadIdx.x;
        #pragma unroll
        for (int k = 0; k < 4; k++) {
            int e = base + k * 256;
            int n = e % ND;
            int t = e / ND;
            int j = t & 1;
            int b = t >> 1;
            g_xT[e] = X4[((size_t)b * ND + n) * 2 + j];
        }
    }
}

// ---------------- Kernel 2: fused priors + routing ----------------
__global__ __launch_bounds__(THREADS, 1)
void caps_routing_kernel(float* __restrict__ out)
{
    __shared__ float vred[2][NWARPS * 32];   // double-buffered by iteration
    __shared__ float spred[2][NWARPS * 2];
    __shared__ float outv[32];

    const int tid  = threadIdx.x;
    const int lane = tid & 31;
    const int w    = tid >> 5;           // 0..17
    const int c    = blockIdx.x >> 6;
    const int b0   = (blockIdx.x & 63) * 2;

    const float4* __restrict__ xr0 = g_xT + (size_t)(b0 * 2) * ND;
    const float4* __restrict__ xr1 = g_xT + (size_t)((b0 + 1) * 2) * ND;
    const float4* __restrict__ wbase = g_Wt + (size_t)c * 32 * ND;

    // -------- Phase A: priors, both nodes fully register-resident --------
    float priA0[16], priA1[16];   // node tid      (batch 0 / 1)
    float priB0[16], priB1[16];   // node tid+576  (batch 0 / 1)

    #pragma unroll
    for (int rep = 0; rep < 2; rep++) {
        const int n = tid + rep * HALF;
        float4 u0 = xr0[n], u1 = xr0[ND + n];
        float4 u2 = xr1[n], u3 = xr1[ND + n];
        float xa[8] = {u0.x, u0.y, u0.z, u0.w, u1.x, u1.y, u1.z, u1.w};
        float xb[8] = {u2.x, u2.y, u2.z, u2.w, u3.x, u3.y, u3.z, u3.w};

        float* a0 = rep ? priB0 : priA0;
        float* a1 = rep ? priB1 : priA1;
        #pragma unroll
        for (int o = 0; o < 16; o++) { a0[o] = 0.f; a1[o] = 0.f; }

        const float4* wp = wbase + n;
        #pragma unroll
        for (int i = 0; i < 8; i++) {
            const float va = xa[i], vb = xb[i];
            #pragma unroll
            for (int q = 0; q < 4; q++) {
                float4 wv = wp[(size_t)(i * 4 + q) * ND];
                a0[4*q+0] += va * wv.x; a0[4*q+1] += va * wv.y;
                a0[4*q+2] += va * wv.z; a0[4*q+3] += va * wv.w;
                a1[4*q+0] += vb * wv.x; a1[4*q+1] += vb * wv.y;
                a1[4*q+2] += vb * wv.z; a1[4*q+3] += vb * wv.w;
            }
        }
    }

    float la0 = 0.f, la1 = 0.f, lb0 = 0.f, lb1 = 0.f;      // logits

    // ---------------- Phase B: iterations 0..2 ----------------
    #pragma unroll 1
    for (int it = 0; it < 3; it++) {
        const int buf = it & 1;
        float v0[16], v1[16];
        float sp0 = 0.f, sp1 = 0.f;

        if (it == 0) {
            // logits == 0: attention exactly uniform; S = ND.
            #pragma unroll
            for (int o = 0; o < 16; o++) {
                v0[o] = priB0[o] + priA0[o];
                v1[o] = priB1[o] + priA1[o];
            }
        } else {
            // fused: logit update -> exp -> weighted accumulation.
            // batch 0
            {
                float dA = 0.f, dB = 0.f;
                #pragma unroll
                for (int o = 0; o < 16; o++) {
                    const float ov = outv[o];
                    dA += ov * priA0[o];
                    dB += ov * priB0[o];
                }
                la0 += dA; lb0 += dB;
                float eA = __expf(la0);
                float eB = __expf(lb0);
                sp0 = eA + eB;
                #pragma unroll
                for (int o = 0; o < 16; o++)
                    v0[o] = eA * priA0[o] + eB * priB0[o];
            }
            // batch 1
            {
                float dA = 0.f, dB = 0.f;
                #pragma unroll
                for (int o = 0; o < 16; o++) {
                    const float ov = outv[16 + o];
                    dA += ov * priA1[o];
                    dB += ov * priB1[o];
                }
                la1 += dA; lb1 += dB;
                float eA = __expf(la1);
                float eB = __expf(lb1);
                sp1 = eA + eB;
                #pragma unroll
                for (int o = 0; o < 16; o++)
                    v1[o] = eA * priA1[o] + eB * priB1[o];
            }
        }

        // batch-merging component-splitting warp reduce (31 shfl):
        // bit-16 merges batches; bits 8/4/2/1 split components.
        float v[16];
        #pragma unroll
        for (int k = 0; k < 16; k++) {
            float s = (lane & 16) ? v0[k] : v1[k];
            float r = __shfl_xor_sync(0xffffffffu, s, 16);
            v[k] = ((lane & 16) ? v1[k] : v0[k]) + r;
        }
        #pragma unroll
        for (int k = 0; k < 8; k++) {
            float s = (lane & 8) ? v[k] : v[k + 8];
            float r = __shfl_xor_sync(0xffffffffu, s, 8);
            v[k] = ((lane & 8) ? v[k + 8] : v[k]) + r;
        }
        #pragma unroll
        for (int k = 0; k < 4; k++) {
            float s = (lane & 4) ? v[k] : v[k + 4];
            float r = __shfl_xor_sync(0xffffffffu, s, 4);
            v[k] = ((lane & 4) ? v[k + 4] : v[k]) + r;
        }
        #pragma unroll
        for (int k = 0; k < 2; k++) {
            float s = (lane & 2) ? v[k] : v[k + 2];
            float r = __shfl_xor_sync(0xffffffffu, s, 2);
            v[k] = ((lane & 2) ? v[k + 2] : v[k]) + r;
        }
        {
            float s = (lane & 1) ? v[0] : v[1];
            float r = __shfl_xor_sync(0xffffffffu, s, 1);
            v[0] = ((lane & 1) ? v[1] : v[0]) + r;
        }
        vred[buf][w * 32 + lane] = v[0];

        if (it > 0) {   // sp: merge batches then butterfly
            float s = (lane & 16) ? sp0 : sp1;
            float r = __shfl_xor_sync(0xffffffffu, s, 16);
            float sp = ((lane & 16) ? sp1 : sp0) + r;
            #pragma unroll
            for (int d = 8; d; d >>= 1)
                sp += __shfl_xor_sync(0xffffffffu, sp, d);
            if ((lane & 15) == 0) spred[buf][w * 2 + (lane >> 4)] = sp;
        }
        __syncthreads();   // the ONLY barrier this iteration

        // --- redundant final reduce + squash: EVERY warp computes the
        // identical result; outv writes are bit-identical (benign race). ---
        {
            const int fb = lane >> 4;
            float O = 0.f;
            #pragma unroll
            for (int j = 0; j < NWARPS; j++) O += vred[buf][j * 32 + lane];
            float S;
            if (it == 0) {
                S = (float)ND;
            } else {
                S = 0.f;
                #pragma unroll
                for (int j = 0; j < NWARPS; j++) S += spred[buf][j * 2 + fb];
            }
            float t = O / S;
            float sq = t * t;
            #pragma unroll
            for (int d = 8; d; d >>= 1)
                sq += __shfl_xor_sync(0xffffffffu, sq, d);
            float scale = sq / ((1.f + sq) * sqrtf(sq + 1e-8f));
            float val = t * scale;
            if (it < 2)
                outv[lane] = val;                   // identical in all warps
            else if (w == 0)
                out[((size_t)(c * BD + b0 + fb)) * OUTD + (lane & 15)] = val;
        }
    }
}

extern "C" void kernel_launch(void* const* d_in, const int* in_sizes, int n_in,
                              void* d_out, int out_size)
{
    const float* x = (const float*)d_in[0];
    const float* W = (const float*)d_in[1];
    // defensive: identify by size (x: 1,179,648 ; W: 1,474,560)
    if (n_in >= 2 && in_sizes[0] == CCAP * ND * 8 * OUTD) {
        x = (const float*)d_in[1];
        W = (const float*)d_in[0];
    }
    float* out = (float*)d_out;

    transpose_inputs_kernel<<<TP_WBLOCKS + TP_XBLOCKS, 256>>>(
        (const float4*)W, (const float4*)x);

    caps_routing_kernel<<<NBLOCKS, THREADS>>>(out);
}

// round 14
// speedup vs baseline: 1.0681x; 1.0681x over previous
#include <cuda_runtime.h>

// CapsuleLayer dynamic routing. C=10,B=128,N=1152,IN=8,OUT=16, 3 iters.
//   1) tiled transpose W -> Wt4[c][j][n]; simple transpose x -> xT4[b][j][n]
//   2) fused priors + routing, one CTA per (c, batch-pair), 576 threads.
// All priors register-resident, PACKED as f32x2 pairs of adjacent OUT
// components (fma.rn.f32x2: PTX-only dual-FMA; W float4 loads reinterpret
// as ulonglong2 so packed operands are free). R12 reduce structure
// (warp butterfly -> vred -> warp-0 squash, two barriers/iteration).
// Shift-free softmax (exact), fused logit-update/accumulation sweeps;
// iteration 0 uses logits==0 -> uniform attention (S = N).

#define CCAP   10
#define BD     128
#define ND     1152
#define OUTD   16
#define HALF   576
#define THREADS 576
#define NWARPS  18
#define NBLOCKS (CCAP * BD / 2)   // 640

#define WT_ELEMS (CCAP * 32 * ND)   // 368,640 float4 (5.9 MB)
#define XT_ELEMS (BD * 2 * ND)      // 294,912 float4 (4.7 MB)

__device__ float4 g_Wt[WT_ELEMS];
__device__ float4 g_xT[XT_ELEMS];

typedef unsigned long long u64;

__device__ __forceinline__ u64 pk2(float a, float b) {
    u64 r; asm("mov.b64 %0, {%1, %2};" : "=l"(r) : "f"(a), "f"(b)); return r;
}
__device__ __forceinline__ void upk2(float& a, float& b, u64 v) {
    asm("mov.b64 {%0, %1}, %2;" : "=f"(a), "=f"(b) : "l"(v));
}
__device__ __forceinline__ u64 ffma2(u64 a, u64 b, u64 c) {
    u64 d; asm("fma.rn.f32x2 %0, %1, %2, %3;" : "=l"(d) : "l"(a), "l"(b), "l"(c)); return d;
}
__device__ __forceinline__ u64 fmul2(u64 a, u64 b) {
    u64 d; asm("mul.rn.f32x2 %0, %1, %2;" : "=l"(d) : "l"(a), "l"(b)); return d;
}
__device__ __forceinline__ u64 fadd2(u64 a, u64 b) {
    u64 d; asm("add.rn.f32x2 %0, %1, %2;" : "=l"(d) : "l"(a), "l"(b)); return d;
}

// ---------------- Kernel 1: transposes ----------------
#define TP_WBLOCKS (CCAP * 36)          // 360
#define TP_XBLOCKS (XT_ELEMS / 1024)    // 288

__global__ void transpose_inputs_kernel(const float4* __restrict__ W4,
                                        const float4* __restrict__ X4)
{
    if (blockIdx.x < TP_WBLOCKS) {
        __shared__ float4 tile[32][33];
        const int c  = blockIdx.x / 36;
        const int n0 = (blockIdx.x % 36) * 32;
        #pragma unroll
        for (int k = 0; k < 4; k++) {
            int flat = threadIdx.x + k * 256;
            int jr = flat & 31, nr = flat >> 5;
            tile[jr][nr] = W4[((size_t)(c * ND + n0 + nr)) * 32 + jr];
        }
        __syncthreads();
        #pragma unroll
        for (int k = 0; k < 4; k++) {
            int flat = threadIdx.x + k * 256;
            int nr = flat & 31, jr = flat >> 5;
            g_Wt[(size_t)(c * 32 + jr) * ND + n0 + nr] = tile[jr][nr];
        }
    } else {
        int base = (blockIdx.x - TP_WBLOCKS) * 1024 + threadIdx.x;
        #pragma unroll
        for (int k = 0; k < 4; k++) {
            int e = base + k * 256;
            int n = e % ND;
            int t = e / ND;
            int j = t & 1;
            int b = t >> 1;
            g_xT[e] = X4[((size_t)b * ND + n) * 2 + j];
        }
    }
}

// ---------------- Kernel 2: fused priors + routing ----------------
__global__ __launch_bounds__(THREADS, 1)
void caps_routing_kernel(float* __restrict__ out)
{
    __shared__ float vred[NWARPS * 32];
    __shared__ float spred[NWARPS * 2];
    __shared__ float outv[32];

    const int tid  = threadIdx.x;
    const int lane = tid & 31;
    const int w    = tid >> 5;           // 0..17
    const int c    = blockIdx.x >> 6;
    const int b0   = (blockIdx.x & 63) * 2;

    const float4* __restrict__ xr0 = g_xT + (size_t)(b0 * 2) * ND;
    const float4* __restrict__ xr1 = g_xT + (size_t)((b0 + 1) * 2) * ND;
    const ulonglong2* __restrict__ wbase =
        (const ulonglong2*)(g_Wt + (size_t)c * 32 * ND);

    // -------- Phase A: priors, packed f32x2 (pairs of OUT components) ----
    u64 pA0[8], pA1[8];   // node tid      (batch 0 / 1), comps (2k, 2k+1)
    u64 pB0[8], pB1[8];   // node tid+576  (batch 0 / 1)

    #pragma unroll
    for (int rep = 0; rep < 2; rep++) {
        const int n = tid + rep * HALF;
        float4 u0 = xr0[n], u1 = xr0[ND + n];
        float4 u2 = xr1[n], u3 = xr1[ND + n];
        float xa[8] = {u0.x, u0.y, u0.z, u0.w, u1.x, u1.y, u1.z, u1.w};
        float xb[8] = {u2.x, u2.y, u2.z, u2.w, u3.x, u3.y, u3.z, u3.w};

        u64* a0 = rep ? pB0 : pA0;
        u64* a1 = rep ? pB1 : pA1;
        #pragma unroll
        for (int k = 0; k < 8; k++) { a0[k] = 0ull; a1[k] = 0ull; }

        const ulonglong2* wp = wbase + n;
        #pragma unroll
        for (int i = 0; i < 8; i++) {
            const u64 va2 = pk2(xa[i], xa[i]);
            const u64 vb2 = pk2(xb[i], xb[i]);
            #pragma unroll
            for (int q = 0; q < 4; q++) {
                ulonglong2 wv = wp[(size_t)(i * 4 + q) * ND];
                a0[2*q+0] = ffma2(va2, wv.x, a0[2*q+0]);
                a0[2*q+1] = ffma2(va2, wv.y, a0[2*q+1]);
                a1[2*q+0] = ffma2(vb2, wv.x, a1[2*q+0]);
                a1[2*q+1] = ffma2(vb2, wv.y, a1[2*q+1]);
            }
        }
    }

    float la0 = 0.f, la1 = 0.f, lb0 = 0.f, lb1 = 0.f;      // logits

    // ---------------- Phase B: iterations 0..2 ----------------
    #pragma unroll 1
    for (int it = 0; it < 3; it++) {
        u64 v02[8], v12[8];
        float sp0 = 0.f, sp1 = 0.f;

        if (it == 0) {
            // logits == 0: attention exactly uniform; S = ND.
            #pragma unroll
            for (int k = 0; k < 8; k++) {
                v02[k] = fadd2(pB0[k], pA0[k]);
                v12[k] = fadd2(pB1[k], pA1[k]);
            }
        } else {
            // fused: logit update -> exp -> weighted accumulation.
            // batch 0
            {
                u64 tA = 0ull, tB = 0ull;
                #pragma unroll
                for (int k = 0; k < 8; k++) {
                    const u64 ov2 = *reinterpret_cast<const u64*>(&outv[2*k]);
                    tA = ffma2(ov2, pA0[k], tA);
                    tB = ffma2(ov2, pB0[k], tB);
                }
                float aL, aH, bL, bH;
                upk2(aL, aH, tA); upk2(bL, bH, tB);
                la0 += aL + aH; lb0 += bL + bH;
                float eA = __expf(la0);
                float eB = __expf(lb0);
                sp0 = eA + eB;
                const u64 eA2 = pk2(eA, eA), eB2 = pk2(eB, eB);
                #pragma unroll
                for (int k = 0; k < 8; k++)
                    v02[k] = ffma2(eA2, pA0[k], fmul2(eB2, pB0[k]));
            }
            // batch 1
            {
                u64 tA = 0ull, tB = 0ull;
                #pragma unroll
                for (int k = 0; k < 8; k++) {
                    const u64 ov2 = *reinterpret_cast<const u64*>(&outv[16 + 2*k]);
                    tA = ffma2(ov2, pA1[k], tA);
                    tB = ffma2(ov2, pB1[k], tB);
                }
                float aL, aH, bL, bH;
                upk2(aL, aH, tA); upk2(bL, bH, tB);
                la1 += aL + aH; lb1 += bL + bH;
                float eA = __expf(la1);
                float eB = __expf(lb1);
                sp1 = eA + eB;
                const u64 eA2 = pk2(eA, eA), eB2 = pk2(eB, eB);
                #pragma unroll
                for (int k = 0; k < 8; k++)
                    v12[k] = ffma2(eA2, pA1[k], fmul2(eB2, pB1[k]));
            }
        }

        // unpack for the scalar shuffle butterfly
        float v0[16], v1[16];
        #pragma unroll
        for (int k = 0; k < 8; k++) {
            upk2(v0[2*k], v0[2*k+1], v02[k]);
            upk2(v1[2*k], v1[2*k+1], v12[k]);
        }

        // batch-merging component-splitting warp reduce (31 shfl):
        // bit-16 merges batches; bits 8/4/2/1 split components.
        float v[16];
        #pragma unroll
        for (int k = 0; k < 16; k++) {
            float s = (lane & 16) ? v0[k] : v1[k];
            float r = __shfl_xor_sync(0xffffffffu, s, 16);
            v[k] = ((lane & 16) ? v1[k] : v0[k]) + r;
        }
        #pragma unroll
        for (int k = 0; k < 8; k++) {
            float s = (lane & 8) ? v[k] : v[k + 8];
            float r = __shfl_xor_sync(0xffffffffu, s, 8);
            v[k] = ((lane & 8) ? v[k + 8] : v[k]) + r;
        }
        #pragma unroll
        for (int k = 0; k < 4; k++) {
            float s = (lane & 4) ? v[k] : v[k + 4];
            float r = __shfl_xor_sync(0xffffffffu, s, 4);
            v[k] = ((lane & 4) ? v[k + 4] : v[k]) + r;
        }
        #pragma unroll
        for (int k = 0; k < 2; k++) {
            float s = (lane & 2) ? v[k] : v[k + 2];
            float r = __shfl_xor_sync(0xffffffffu, s, 2);
            v[k] = ((lane & 2) ? v[k + 2] : v[k]) + r;
        }
        {
            float s = (lane & 1) ? v[0] : v[1];
            float r = __shfl_xor_sync(0xffffffffu, s, 1);
            v[0] = ((lane & 1) ? v[1] : v[0]) + r;
        }
        vred[w * 32 + lane] = v[0];

        if (it > 0) {   // sp: merge batches then butterfly
            float s = (lane & 16) ? sp0 : sp1;
            float r = __shfl_xor_sync(0xffffffffu, s, 16);
            float sp = ((lane & 16) ? sp1 : sp0) + r;
            #pragma unroll
            for (int d = 8; d; d >>= 1)
                sp += __shfl_xor_sync(0xffffffffu, sp, d);
            if ((lane & 15) == 0) spred[w * 2 + (lane >> 4)] = sp;
        }
        __syncthreads();

        // --- final 18-way reduce + squash (warp 0: lanes 0-15 bb0, 16-31 bb1) ---
        if (tid < 32) {
            const int fb = tid >> 4;
            float O = 0.f;
            #pragma unroll
            for (int j = 0; j < NWARPS; j++) O += vred[j * 32 + tid];
            float S;
            if (it == 0) {
                S = (float)ND;
            } else {
                S = 0.f;
                #pragma unroll
                for (int j = 0; j < NWARPS; j++) S += spred[j * 2 + fb];
            }
            float t = O / S;
            float sq = t * t;
            #pragma unroll
            for (int d = 8; d; d >>= 1)
                sq += __shfl_xor_sync(0xffffffffu, sq, d);
            float scale = sq / ((1.f + sq) * sqrtf(sq + 1e-8f));
            float val = t * scale;
            outv[tid] = val;
            if (it == 2)
                out[((size_t)(c * BD + b0 + fb)) * OUTD + (tid & 15)] = val;
        }
        __syncthreads();
    }
}

extern "C" void kernel_launch(void* const* d_in, const int* in_sizes, int n_in,
                              void* d_out, int out_size)
{
    const float* x = (const float*)d_in[0];
    const float* W = (const float*)d_in[1];
    // defensive: identify by size (x: 1,179,648 ; W: 1,474,560)
    if (n_in >= 2 && in_sizes[0] == CCAP * ND * 8 * OUTD) {
        x = (const float*)d_in[1];
        W = (const float*)d_in[0];
    }
    float* out = (float*)d_out;

    transpose_inputs_kernel<<<TP_WBLOCKS + TP_XBLOCKS, 256>>>(
        (const float4*)W, (const float4*)x);

    caps_routing_kernel<<<NBLOCKS, THREADS>>>(out);
}